// round 17
// baseline (speedup 1.0000x reference)
#include <cuda_runtime.h>
#include <cuda_fp16.h>
#include <math.h>
#include <stdint.h>

#define BB 8
#define NN 2048
#define DD 1024
typedef long long ll;
typedef __half fp16;

// ---------------- scratch (allocation-free rule: __device__ globals) ----------
__device__ fp16  g_uh[BB * NN * DD];       // normalized pairs (GEMM1 fused out)
__device__ fp16  g_v16[BB * NN * DD];      // values, fp16 (n,d) natural layout
__device__ fp16  g_c[(ll)BB * NN * NN];    // coupling (UNNORMALIZED)
__device__ float g_rs[BB * NN];            // coupling row sums
__device__ fp16  g_sh[BB * NN * DD];       // S fp16
__device__ fp16  g_wh[DD * DD];            // W_in
__device__ fp16  g_wo[DD * DD];            // W_out

// ---------------- PTX helpers ------------------------------------------------
__device__ __forceinline__ uint32_t smem_u32(const void* p) {
    uint32_t a;
    asm("{ .reg .u64 t; cvta.to.shared.u64 t, %1; cvt.u32.u64 %0, t; }" : "=r"(a) : "l"(p));
    return a;
}
__device__ __forceinline__ void cpa16(uint32_t d, const void* s) {
    asm volatile("cp.async.cg.shared.global [%0], [%1], 16;" :: "r"(d), "l"(s));
}
__device__ __forceinline__ void cp_commit() { asm volatile("cp.async.commit_group;"); }
template <int N> __device__ __forceinline__ void cp_wait() {
    asm volatile("cp.async.wait_group %0;" :: "n"(N));
}
__device__ __forceinline__ void mma16(float* c, const uint32_t* a, const uint32_t* b) {
    asm volatile(
        "mma.sync.aligned.m16n8k16.row.col.f32.f16.f16.f32 "
        "{%0,%1,%2,%3}, {%4,%5,%6,%7}, {%8,%9}, {%0,%1,%2,%3};"
        : "+f"(c[0]), "+f"(c[1]), "+f"(c[2]), "+f"(c[3])
        : "r"(a[0]), "r"(a[1]), "r"(a[2]), "r"(a[3]), "r"(b[0]), "r"(b[1]));
}
__device__ __forceinline__ void ldsm4(uint32_t* r, uint32_t addr) {
    asm volatile("ldmatrix.sync.aligned.m8n8.x4.shared.b16 {%0,%1,%2,%3}, [%4];"
        : "=r"(r[0]), "=r"(r[1]), "=r"(r[2]), "=r"(r[3]) : "r"(addr));
}
__device__ __forceinline__ void ldsm4t(uint32_t* r, uint32_t addr) {
    asm volatile("ldmatrix.sync.aligned.m8n8.x4.trans.shared.b16 {%0,%1,%2,%3}, [%4];"
        : "=r"(r[0]), "=r"(r[1]), "=r"(r[2]), "=r"(r[3]) : "r"(addr));
}

// Tile geometry: 128x128 block, BK=64, 8 warps (2x4), warp tile 64x32. 3 stages.
#define ROWB 144
#define TILE_B (128 * ROWB)          // 18432 B, 128x64 K-major tile
#define BROWB 272
#define BTILE_TR (64 * BROWB)        // 17408 B, 64x128 N-major tile

// EPI: 3 = fused pairnorm -> fp16; 5 = gate-scale -> fp16; 6 = row-normalized f32.
// TRB: B given as [Ktot, ldB] row-major (N-major tile + ldmatrix.trans).
template <int EPI, bool TRB>
__global__ __launch_bounds__(256) void hgemm(
    const fp16* __restrict__ Ag, const fp16* __restrict__ Bg,
    float* __restrict__ Cg, int K, int ldC, int ldB,
    ll sA, ll sB, ll sC,
    const float* __restrict__ rowAux, ll sAux)
{
    extern __shared__ char dsm[];
    const int tid = threadIdx.x, lane = tid & 31, warp = tid >> 5;
    const int mq = lane >> 2, kq = lane & 3;
    const int wm = (warp >> 2) * 64, wn = (warp & 3) * 32;
    const int b = blockIdx.z;
    const int rowBlock = blockIdx.y * 128, colBlock = blockIdx.x * 128;

    const fp16* Ap = Ag + (ll)b * sA + (ll)rowBlock * K;
    const fp16* Bp = TRB ? (Bg + (ll)b * sB + colBlock)
                         : (Bg + (ll)b * sB + (ll)colBlock * K);
    float* C = Cg + (ll)b * sC;

    const uint32_t STAGE = TILE_B + (TRB ? BTILE_TR : TILE_B);
    uint32_t smem = smem_u32(dsm);

    const int sub = lane >> 3, l7 = lane & 7;
    const uint32_t lmoff  = (uint32_t)(((sub & 1) * 8 + l7) * ROWB  + (sub >> 1) * 16);
    const uint32_t lmoffB = (uint32_t)(((sub & 1) * 8 + l7) * BROWB + (sub >> 1) * 16);

    float acc[4][4][4];
#pragma unroll
    for (int i = 0; i < 4; i++)
#pragma unroll
        for (int j = 0; j < 4; j++)
#pragma unroll
            for (int r = 0; r < 4; r++) acc[i][j][r] = 0.0f;

    auto load_A = [&](uint32_t ts, int k0) {
#pragma unroll
        for (int h = 0; h < 4; h++) {
            int f = tid + h * 256;
            int r = f >> 3, c = f & 7;
            cpa16(ts + r * ROWB + c * 16, Ap + (ll)r * K + k0 + c * 8);
        }
    };
    auto load_B = [&](uint32_t ts, int k0) {
        if (TRB) {
#pragma unroll
            for (int h = 0; h < 4; h++) {
                int f = tid + h * 256;
                int r = f >> 4, c = f & 15;
                cpa16(ts + r * BROWB + c * 16, Bp + (ll)(k0 + r) * ldB + c * 8);
            }
        } else {
#pragma unroll
            for (int h = 0; h < 4; h++) {
                int f = tid + h * 256;
                int r = f >> 3, c = f & 7;
                cpa16(ts + r * ROWB + c * 16, Bp + (ll)r * K + k0 + c * 8);
            }
        }
    };
    auto prefetch = [&](int ch) {
        uint32_t bo = smem + (uint32_t)(ch % 3) * STAGE;
        int k0 = ch * 64;
        load_A(bo, k0);
        load_B(bo + TILE_B, k0);
        cp_commit();
    };

    const int CH = K >> 6;
    prefetch(0);
    prefetch(1);

    for (int ch = 0; ch < CH; ++ch) {
        cp_wait<1>();
        __syncthreads();
        if (ch + 2 < CH) prefetch(ch + 2);
        else             cp_commit();

        uint32_t bo = smem + (uint32_t)(ch % 3) * STAGE;
        uint32_t As = bo, Bs = bo + TILE_B;

#pragma unroll
        for (int ks = 0; ks < 4; ks++) {
            uint32_t af[4][4], bfr[4][2];
#pragma unroll
            for (int i = 0; i < 4; i++)
                ldsm4(af[i], As + (uint32_t)(wm + i * 16) * ROWB + lmoff
                              + (uint32_t)ks * 32);
#pragma unroll
            for (int jj = 0; jj < 2; jj++) {
                uint32_t t[4];
                if (TRB) {
                    ldsm4t(t, Bs + (uint32_t)ks * 16 * BROWB
                                 + (uint32_t)(wn + jj * 16) * 2 + lmoffB);
                } else {
                    ldsm4(t, Bs + (uint32_t)(wn + jj * 16) * ROWB + lmoff
                                + (uint32_t)ks * 32);
                }
                bfr[2 * jj][0] = t[0]; bfr[2 * jj + 1][0] = TRB ? t[2] : t[1];
                bfr[2 * jj][1] = TRB ? t[1] : t[2]; bfr[2 * jj + 1][1] = t[3];
            }
#pragma unroll
            for (int i = 0; i < 4; i++)
#pragma unroll
                for (int j = 0; j < 4; j++)
                    mma16(acc[i][j], af[i], bfr[j]);
        }
    }

    // ---- epilogue ----
#pragma unroll
    for (int i = 0; i < 4; i++) {
        int r0 = rowBlock + wm + i * 16 + mq;
#pragma unroll
        for (int j = 0; j < 4; j++) {
            int c0 = colBlock + wn + j * 8 + 2 * kq;
#pragma unroll
            for (int h = 0; h < 2; h++) {
                int rr = r0 + h * 8;
                float x = acc[i][j][h * 2 + 0];
                float y = acc[i][j][h * 2 + 1];
                ll off = (ll)rr * ldC + c0;
                if (EPI == 3) {
                    float xn = x + 1e-8f, yn = y + 1e-8f;
                    float inv = rsqrtf(xn * xn + yn * yn);
                    __half2 h2 = __floats2half2_rn(xn * inv, yn * inv);
                    *(uint32_t*)((fp16*)Cg + (ll)b * sC + off) = *(uint32_t*)&h2;
                } else if (EPI == 5) {
                    float g = rowAux[rr];
                    __half2 h2 = __floats2half2_rn(x * g, y * g);
                    *(uint32_t*)((fp16*)Cg + (ll)b * sC + off) = *(uint32_t*)&h2;
                } else {  // EPI == 6: scale by 1/rowsum
                    float inv = 1.0f / (rowAux[(ll)b * sAux + rr] + 1e-8f);
                    *(float2*)(C + off) = make_float2(x * inv, y * inv);
                }
            }
        }
    }
}

// ============ symmetric resonance GEMM + fused coupling ======================
// Computes racc_new (output, both triangles), plus UNNORMALIZED coupling
// c = sigmoid(cond*racc_new)*g_send*g_recv (zero diag) -> cOut, plus per-row
// sums of c -> rsum (atomicAdd).
__global__ __launch_bounds__(256, 2) void hgemm_sym(
    const fp16* __restrict__ Ag, float* __restrict__ Cg, int K, int ldC,
    ll sA, ll sC, const float* __restrict__ raccIn, float resScale,
    const float* __restrict__ gates, const float* __restrict__ condPtr,
    fp16* __restrict__ cOut, float* __restrict__ rsum)
{
    extern __shared__ char dsm[];
    const int tid = threadIdx.x, lane = tid & 31, warp = tid >> 5;
    const int mq = lane >> 2, kq = lane & 3;
    const int wm = (warp >> 2) * 64, wn = (warp & 3) * 32;
    const int b = blockIdx.z;

    int T = ldC >> 7;
    int t = blockIdx.x, bi = 0;
    while (t >= T - bi) { t -= T - bi; bi++; }
    const int rowBlock = bi * 128;
    const int colBlock = (bi + t) * 128;

    const fp16* Ap = Ag + (ll)b * sA + (ll)rowBlock * K;
    const fp16* Bp = Ag + (ll)b * sA + (ll)colBlock * K;
    float* C = Cg + (ll)b * sC;

    const uint32_t STAGE = 2u * TILE_B;
    uint32_t smem = smem_u32(dsm);

    const int sub = lane >> 3, l7 = lane & 7;
    const uint32_t lmoff = (uint32_t)(((sub & 1) * 8 + l7) * ROWB + (sub >> 1) * 16);

    float acc[4][4][4];
#pragma unroll
    for (int i = 0; i < 4; i++)
#pragma unroll
        for (int j = 0; j < 4; j++)
#pragma unroll
            for (int r = 0; r < 4; r++) acc[i][j][r] = 0.0f;

    auto load_tile = [&](uint32_t ts, const fp16* g, int k0) {
#pragma unroll
        for (int h = 0; h < 4; h++) {
            int f = tid + h * 256;
            int r = f >> 3, c = f & 7;
            cpa16(ts + r * ROWB + c * 16, g + (ll)r * K + k0 + c * 8);
        }
    };
    auto prefetch = [&](int ch) {
        uint32_t bo = smem + (uint32_t)(ch % 3) * STAGE;
        int k0 = ch * 64;
        load_tile(bo, Ap, k0);
        load_tile(bo + TILE_B, Bp, k0);
        cp_commit();
    };

    const int CH = K >> 6;
    prefetch(0);
    prefetch(1);

    for (int ch = 0; ch < CH; ++ch) {
        cp_wait<1>();
        __syncthreads();
        if (ch + 2 < CH) prefetch(ch + 2);
        else             cp_commit();

        uint32_t bo = smem + (uint32_t)(ch % 3) * STAGE;
        uint32_t As = bo, Bs = bo + TILE_B;

#pragma unroll
        for (int ks = 0; ks < 4; ks++) {
            const uint32_t ko = (uint32_t)ks * 32;
            uint32_t af[4][4], bfr[4][2];
#pragma unroll
            for (int i = 0; i < 4; i++)
                ldsm4(af[i], As + (uint32_t)(wm + i * 16) * ROWB + lmoff + ko);
#pragma unroll
            for (int jj = 0; jj < 2; jj++) {
                uint32_t t4[4];
                ldsm4(t4, Bs + (uint32_t)(wn + jj * 16) * ROWB + lmoff + ko);
                bfr[2 * jj][0] = t4[0]; bfr[2 * jj + 1][0] = t4[1];
                bfr[2 * jj][1] = t4[2]; bfr[2 * jj + 1][1] = t4[3];
            }
#pragma unroll
            for (int i = 0; i < 4; i++)
#pragma unroll
                for (int j = 0; j < 4; j++)
                    mma16(acc[i][j], af[i], bfr[j]);
        }
    }

    // ---- epilogue: racc_new + coupling + row sums ----
    const float* raccB = raccIn + (ll)b * sC;
    const float* gB = gates + (ll)b * ldC;
    fp16* cB = cOut + (ll)b * sC;
    float* rsB = rsum + (ll)b * ldC;
    const float cond = fminf(fmaxf(condPtr[0], -5.0f), 5.0f);
    const bool mirror = (rowBlock != colBlock);

    float drow[4][2];   // direct-row partial sums, indexed (i,h)
    float mrow[4][2];   // mirror-row partial sums, indexed (j, 0/1)
#pragma unroll
    for (int a = 0; a < 4; a++) { drow[a][0] = 0.0f; drow[a][1] = 0.0f;
                                  mrow[a][0] = 0.0f; mrow[a][1] = 0.0f; }

#pragma unroll
    for (int i = 0; i < 4; i++) {
        int r0 = rowBlock + wm + i * 16 + mq;
#pragma unroll
        for (int h = 0; h < 2; h++) {
            int rr = r0 + h * 8;
            float grr = gB[rr];
#pragma unroll
            for (int j = 0; j < 4; j++) {
                int c0 = colBlock + wn + j * 8 + 2 * kq;
                float x = acc[i][j][h * 2 + 0];
                float y = acc[i][j][h * 2 + 1];
                ll off = (ll)rr * ldC + c0;
                float2 rv = *(const float2*)(raccB + off);
                float ox = fminf(fmaxf(0.7f * rv.x + resScale * x, -2.0f), 2.0f);
                float oy = fminf(fmaxf(0.7f * rv.y + resScale * y, -2.0f), 2.0f);
                *(float2*)(C + off) = make_float2(ox, oy);

                // coupling (direct): row rr, cols c0, c0+1
                float cx = grr * gB[c0]     / (1.0f + expf(-cond * ox));
                float cy = grr * gB[c0 + 1] / (1.0f + expf(-cond * oy));
                if (rr == c0)     cx = 0.0f;
                if (rr == c0 + 1) cy = 0.0f;
                __half2 h2 = __floats2half2_rn(cx, cy);
                *(uint32_t*)(cB + off) = *(uint32_t*)&h2;
                drow[i][h] += cx + cy;

                if (mirror) {
                    ll t0 = (ll)c0 * ldC + rr;
                    ll t1 = t0 + ldC;
                    float o0 = fminf(fmaxf(0.7f * raccB[t0] + resScale * x, -2.0f), 2.0f);
                    float o1 = fminf(fmaxf(0.7f * raccB[t1] + resScale * y, -2.0f), 2.0f);
                    C[t0] = o0;
                    C[t1] = o1;
                    // coupling (mirror): rows c0 / c0+1, col rr
                    float m0 = gB[c0]     * grr / (1.0f + expf(-cond * o0));
                    float m1 = gB[c0 + 1] * grr / (1.0f + expf(-cond * o1));
                    cB[t0] = __float2half_rn(m0);
                    cB[t1] = __float2half_rn(m1);
                    mrow[j][0] += m0;
                    mrow[j][1] += m1;
                }
            }
        }
    }

    // direct rows: lanes kq=0..3 (4 consecutive) share row rr for fixed (i,h)
#pragma unroll
    for (int i = 0; i < 4; i++)
#pragma unroll
        for (int h = 0; h < 2; h++) {
            float v = drow[i][h];
            v += __shfl_xor_sync(0xffffffffu, v, 1);
            v += __shfl_xor_sync(0xffffffffu, v, 2);
            if (kq == 0) {
                int rr = rowBlock + wm + i * 16 + mq + h * 8;
                atomicAdd(&rsB[rr], v);
            }
        }
    // mirror rows: lanes with same kq (stride-4 lanes) share c0 for fixed j
    if (mirror) {
#pragma unroll
        for (int j = 0; j < 4; j++)
#pragma unroll
            for (int d = 0; d < 2; d++) {
                float v = mrow[j][d];
                v += __shfl_xor_sync(0xffffffffu, v, 4);
                v += __shfl_xor_sync(0xffffffffu, v, 8);
                v += __shfl_xor_sync(0xffffffffu, v, 16);
                if (mq == 0) {
                    int c0 = colBlock + wn + j * 8 + 2 * kq + d;
                    atomicAdd(&rsB[c0], v);
                }
            }
    }
}

// ---------------- elementwise kernels ----------------------------------------
__global__ void conv_s_kernel(const float* __restrict__ S, fp16* __restrict__ Sh) {
    ll i = (ll)blockIdx.x * blockDim.x + threadIdx.x;
    if (i >= (ll)BB * NN * DD) return;
    Sh[i] = __float2half_rn(S[i]);
}

__global__ void conv_w_kernel(const float* __restrict__ Win, const float* __restrict__ Wout,
                              fp16* __restrict__ Wh, fp16* __restrict__ Wo) {
    int i = blockIdx.x * blockDim.x + threadIdx.x;
    if (i >= DD * DD) return;
    Wh[i] = __float2half_rn(Win[i]);
    Wo[i] = __float2half_rn(Wout[i]);
}

// ---------------- launch -----------------------------------------------------
extern "C" void kernel_launch(void* const* d_in, const int* in_sizes, int n_in,
                              void* d_out, int out_size) {
    const float* S    = (const float*)d_in[0];
    const float* G    = (const float*)d_in[1];
    const float* Racc = (const float*)d_in[2];
    const float* Win  = (const float*)d_in[3];
    const float* Wout = (const float*)d_in[4];
    const float* cond = (const float*)d_in[5];

    float* field = (float*)d_out;                 // (B,N,D)
    float* raccO = field + (size_t)BB * NN * DD;  // (B,N,N)

    fp16 *uh, *v16, *c16, *sh, *wh, *wo;
    float* rs;
    cudaGetSymbolAddress((void**)&uh, g_uh);
    cudaGetSymbolAddress((void**)&v16, g_v16);
    cudaGetSymbolAddress((void**)&c16, g_c);
    cudaGetSymbolAddress((void**)&rs, g_rs);
    cudaGetSymbolAddress((void**)&sh, g_sh);
    cudaGetSymbolAddress((void**)&wh, g_wh);
    cudaGetSymbolAddress((void**)&wo, g_wo);

    const int SM_KK = 3 * 2 * TILE_B;               // 110592
    const int SM_TR = 3 * (TILE_B + BTILE_TR);      // 107520
    cudaFuncSetAttribute(hgemm<3, false>, cudaFuncAttributeMaxDynamicSharedMemorySize, SM_KK);
    cudaFuncSetAttribute(hgemm<5, false>, cudaFuncAttributeMaxDynamicSharedMemorySize, SM_KK);
    cudaFuncSetAttribute(hgemm<6, true>,  cudaFuncAttributeMaxDynamicSharedMemorySize, SM_TR);
    cudaFuncSetAttribute(hgemm_sym, cudaFuncAttributeMaxDynamicSharedMemorySize, SM_KK);
    cudaFuncSetAttribute(hgemm<3, false>, cudaFuncAttributePreferredSharedMemoryCarveout, 100);
    cudaFuncSetAttribute(hgemm<5, false>, cudaFuncAttributePreferredSharedMemoryCarveout, 100);
    cudaFuncSetAttribute(hgemm<6, true>,  cudaFuncAttributePreferredSharedMemoryCarveout, 100);
    cudaFuncSetAttribute(hgemm_sym, cudaFuncAttributePreferredSharedMemoryCarveout, 100);

    const ll M1 = (ll)BB * NN;  // 16384

    // 0. row-sum buffer zero + conversions
    cudaMemsetAsync(rs, 0, (size_t)BB * NN * sizeof(float));
    conv_s_kernel<<<(int)((M1 * DD + 255) / 256), 256>>>(S, sh);
    conv_w_kernel<<<(DD * DD + 255) / 256, 256>>>(Win, Wout, wh, wo);

    // 1+2. uh = pairnorm(S @ Win^T) fused
    hgemm<3, false><<<dim3(DD / 128, (int)(M1 / 128), 1), 256, SM_KK>>>(
        sh, wh, (float*)uh, DD, DD, DD, 0, 0, 0, nullptr, 0);

    // 3+4. raccO = clip(...); c16 = unnormalized coupling; rs = row sums
    hgemm_sym<<<dim3(136, 1, BB), 256, SM_KK>>>(
        uh, raccO, DD, NN, (ll)NN * DD, (ll)NN * NN, Racc, 0.3f / (float)(DD / 2),
        G, cond, c16, rs);

    // 5. v16 = (S @ Wout^T) * g   (gate in f32 epilogue)
    hgemm<5, false><<<dim3(DD / 128, (int)(M1 / 128), 1), 256, SM_KK>>>(
        sh, wo, (float*)v16, DD, DD, DD, 0, 0, 0, G, 0);

    // 6. field = (c16 @ v16) / rowsum   (row-normalization folded into epilogue)
    hgemm<6, true><<<dim3(DD / 128, NN / 128, BB), 256, SM_TR>>>(
        c16, v16, field, NN, DD, DD,
        (ll)NN * NN, (ll)NN * DD, (ll)NN * DD, rs, NN);
}